// round 10
// baseline (speedup 1.0000x reference)
#include <cuda_runtime.h>
#include <math_constants.h>

// Inputs (metadata order):
//  0: graph_embed   [B, 128]  f32
//  1: tpl_embedding [V+1,128] f32
//  2: cand_idx      [T]       i32
//  3: seg_ids       [T]       i32 (sorted)
//  4: target_pos    [B]       i32 (absolute index into T)
// Output: [B] f32  log_prob of target per segment.

#define MAX_B 8192
__device__ int g_offsets[MAX_B + 1];

// Vectorized boundary finder: each thread scans 4 consecutive seg_ids.
// Triggers programmatic launch of the main kernel ASAP.
__global__ void build_offsets_kernel(const int* __restrict__ seg_ids, int T, int B) {
#if __CUDA_ARCH__ >= 900
    cudaTriggerProgrammaticLaunchCompletion();
#endif
    const int t4 = (blockIdx.x * blockDim.x + threadIdx.x) * 4;
    if (t4 >= T) return;
    const int4 v = *reinterpret_cast<const int4*>(seg_ids + t4);
    if (t4 == 0) {
        g_offsets[0] = 0;
        g_offsets[B] = T;
    } else {
        const int prev = __ldg(&seg_ids[t4 - 1]);
        if (v.x != prev) g_offsets[v.x] = t4;
    }
    if (v.y != v.x) g_offsets[v.y] = t4 + 1;
    if (v.z != v.y) g_offsets[v.z] = t4 + 2;
    if (v.w != v.z) g_offsets[v.w] = t4 + 3;
}

#define THREADS 64     // 2 warps per CTA
#define SEGS_PER_WARP 2  // single-wave persistent mapping

// One WARP per 2 consecutive segments (single residency wave — no wave-2
// quantization tail). 8 lanes per candidate, 8 candidates in flight per
// sub-step. Indices preloaded coalesced 32-at-a-time, distributed by shuffle.
__global__ __launch_bounds__(THREADS)
void seg_logsoftmax_kernel(const float* __restrict__ graph_embed,
                           const float* __restrict__ tpl,
                           const int*   __restrict__ cand_idx,
                           const int*   __restrict__ target_pos,
                           float*       __restrict__ out,
                           int B) {
    const int lane = threadIdx.x & 31;
    const int warp = threadIdx.x >> 5;
    const int gw   = blockIdx.x * (THREADS / 32) + warp;

    const int sub = lane & 7;   // position within candidate group (8 lanes/cand)
    const int grp = lane >> 3;  // candidate group 0..3

#if __CUDA_ARCH__ >= 900
    cudaGridDependencySynchronize();   // offsets valid past this point
#endif

    const int b_first = gw * SEGS_PER_WARP;

    #pragma unroll
    for (int si = 0; si < SEGS_PER_WARP; si++) {
        const int b = b_first + si;
        if (b >= B) break;

        const int start = g_offsets[b];
        const int end   = g_offsets[b + 1];
        const int tgt   = target_pos[b];

        // graph row chunks for this lane: columns j*32 + sub*4
        const float4* grow = reinterpret_cast<const float4*>(graph_embed + (size_t)b * 128);
        const float4 g0 = grow[0 * 8 + sub];
        const float4 g1 = grow[1 * 8 + sub];
        const float4 g2 = grow[2 * 8 + sub];
        const float4 g3 = grow[3 * 8 + sub];

        float s = 0.0f;      // direct sum of exp(logit); fp32 range is sufficient
        float tlogit = 0.0f;
        bool  have_t = false;

        for (int chunk = start; chunk < end; chunk += 32) {
            // coalesced preload of up to 32 candidate indices (invalid -> row 0)
            const int tl_idx = chunk + lane;
            const int cvec = (tl_idx < end) ? __ldg(&cand_idx[tl_idx]) : 0;
            const int rem = end - chunk;   // > 0

            #pragma unroll
            for (int j = 0; j < 32; j += 8) {
                if (j >= rem) break;       // warp-uniform

                const int idxA = chunk + j + grp;
                const int idxB = chunk + j + 4 + grp;
                const bool vA = (idxA < end);
                const bool vB = (idxB < end);
                const int cA = __shfl_sync(0xFFFFFFFFu, cvec, j + grp);
                const int cB = __shfl_sync(0xFFFFFFFFu, cvec, j + 4 + grp);

                const float4* ta = reinterpret_cast<const float4*>(tpl + (size_t)cA * 128);
                const float4* tb = reinterpret_cast<const float4*>(tpl + (size_t)cB * 128);
                const float4 a0 = ta[0 * 8 + sub];
                const float4 a1 = ta[1 * 8 + sub];
                const float4 a2 = ta[2 * 8 + sub];
                const float4 a3 = ta[3 * 8 + sub];
                const float4 b0 = tb[0 * 8 + sub];
                const float4 b1 = tb[1 * 8 + sub];
                const float4 b2 = tb[2 * 8 + sub];
                const float4 b3 = tb[3 * 8 + sub];

                float dA;
                dA  = g0.x * a0.x; dA += g0.y * a0.y; dA += g0.z * a0.z; dA += g0.w * a0.w;
                dA += g1.x * a1.x; dA += g1.y * a1.y; dA += g1.z * a1.z; dA += g1.w * a1.w;
                dA += g2.x * a2.x; dA += g2.y * a2.y; dA += g2.z * a2.z; dA += g2.w * a2.w;
                dA += g3.x * a3.x; dA += g3.y * a3.y; dA += g3.z * a3.z; dA += g3.w * a3.w;

                float dB;
                dB  = g0.x * b0.x; dB += g0.y * b0.y; dB += g0.z * b0.z; dB += g0.w * b0.w;
                dB += g1.x * b1.x; dB += g1.y * b1.y; dB += g1.z * b1.z; dB += g1.w * b1.w;
                dB += g2.x * b2.x; dB += g2.y * b2.y; dB += g2.z * b2.z; dB += g2.w * b2.w;
                dB += g3.x * b3.x; dB += g3.y * b3.y; dB += g3.z * b3.z; dB += g3.w * b3.w;

                dA += __shfl_xor_sync(0xFFFFFFFFu, dA, 1);
                dB += __shfl_xor_sync(0xFFFFFFFFu, dB, 1);
                dA += __shfl_xor_sync(0xFFFFFFFFu, dA, 2);
                dB += __shfl_xor_sync(0xFFFFFFFFu, dB, 2);
                dA += __shfl_xor_sync(0xFFFFFFFFu, dA, 4);
                dB += __shfl_xor_sync(0xFFFFFFFFu, dB, 4);

                if (vA) {
                    s += __expf(dA);
                    if (idxA == tgt) { tlogit = dA; have_t = true; }
                }
                if (vB) {
                    s += __expf(dB);
                    if (idxB == tgt) { tlogit = dB; have_t = true; }
                }
            }
        }

        // total sum: the 4 groups hold distinct partial sums (identical within group)
        s += __shfl_xor_sync(0xFFFFFFFFu, s, 8);
        s += __shfl_xor_sync(0xFFFFFFFFu, s, 16);

        // broadcast target logit from whichever group found it
        const unsigned ball = __ballot_sync(0xFFFFFFFFu, have_t);
        const int src = __ffs(ball) - 1;   // tgt is always inside [start, end)
        const float tl = __shfl_sync(0xFFFFFFFFu, tlogit, src);

        if (lane == 0) out[b] = tl - logf(s);
    }
}

extern "C" void kernel_launch(void* const* d_in, const int* in_sizes, int n_in,
                              void* d_out, int out_size) {
    const float* graph_embed = (const float*)d_in[0];
    const float* tpl         = (const float*)d_in[1];
    const int*   cand_idx    = (const int*)d_in[2];
    const int*   seg_ids     = (const int*)d_in[3];
    const int*   target_pos  = (const int*)d_in[4];
    float*       out         = (float*)d_out;

    const int T = in_sizes[2];
    const int B = in_sizes[4];

    const int n4 = (T + 3) / 4;
    build_offsets_kernel<<<(n4 + 255) / 256, 256>>>(seg_ids, T, B);

    // Main kernel: one wave of CTAs, 2 segments per warp, PDL overlap with prologue.
    const int warps_per_cta = THREADS / 32;
    const int segs_per_cta  = warps_per_cta * SEGS_PER_WARP;
    const int nblocks = (B + segs_per_cta - 1) / segs_per_cta;

    cudaLaunchConfig_t cfg = {};
    cfg.gridDim  = dim3((unsigned)nblocks, 1, 1);
    cfg.blockDim = dim3(THREADS, 1, 1);
    cfg.dynamicSmemBytes = 0;
    cfg.stream = 0;
    cudaLaunchAttribute attrs[1];
    attrs[0].id = cudaLaunchAttributeProgrammaticStreamSerialization;
    attrs[0].val.programmaticStreamSerializationAllowed = 1;
    cfg.attrs = attrs;
    cfg.numAttrs = 1;

    cudaLaunchKernelEx(&cfg, seg_logsoftmax_kernel,
                       graph_embed, tpl, cand_idx, target_pos, out, B);
}

// round 12
// speedup vs baseline: 1.0369x; 1.0369x over previous
#include <cuda_runtime.h>
#include <math_constants.h>

// Inputs (metadata order):
//  0: graph_embed   [B, 128]  f32
//  1: tpl_embedding [V+1,128] f32
//  2: cand_idx      [T]       i32
//  3: seg_ids       [T]       i32 (sorted)
//  4: target_pos    [B]       i32 (absolute index into T)
// Output: [B] f32  log_prob of target per segment.

#define MAX_B 8192
__device__ int g_offsets[MAX_B + 1];

// Vectorized boundary finder: each thread scans 4 consecutive seg_ids.
// Triggers programmatic launch of the main kernel ASAP.
__global__ void build_offsets_kernel(const int* __restrict__ seg_ids, int T, int B) {
#if __CUDA_ARCH__ >= 900
    cudaTriggerProgrammaticLaunchCompletion();
#endif
    const int t4 = (blockIdx.x * blockDim.x + threadIdx.x) * 4;
    if (t4 >= T) return;
    const int4 v = *reinterpret_cast<const int4*>(seg_ids + t4);
    if (t4 == 0) {
        g_offsets[0] = 0;
        g_offsets[B] = T;
    } else {
        const int prev = __ldg(&seg_ids[t4 - 1]);
        if (v.x != prev) g_offsets[v.x] = t4;
    }
    if (v.y != v.x) g_offsets[v.y] = t4 + 1;
    if (v.z != v.y) g_offsets[v.z] = t4 + 2;
    if (v.w != v.z) g_offsets[v.w] = t4 + 3;
}

#define THREADS 64   // 2 warps per CTA, one segment per warp

// One WARP per segment. 8 lanes per candidate, 8 candidates in flight per
// sub-step. Indices preloaded coalesced 32-at-a-time, distributed by shuffle.
// minBlocksPerMultiprocessor=20 caps regs at 51 to raise residency 18->20 CTAs/SM.
__global__ __launch_bounds__(THREADS, 20)
void seg_logsoftmax_kernel(const float* __restrict__ graph_embed,
                           const float* __restrict__ tpl,
                           const int*   __restrict__ cand_idx,
                           const int*   __restrict__ target_pos,
                           float*       __restrict__ out,
                           int B) {
    const int lane = threadIdx.x & 31;
    const int warp = threadIdx.x >> 5;
    const int b    = blockIdx.x * (THREADS / 32) + warp;
    if (b >= B) {
#if __CUDA_ARCH__ >= 900
        cudaGridDependencySynchronize();
#endif
        return;
    }

    const int sub = lane & 7;   // position within candidate group (8 lanes/cand)
    const int grp = lane >> 3;  // candidate group 0..3

    // ---- offset-independent work (overlaps with prologue kernel) ----
    const int tgt = target_pos[b];

    const float4* grow = reinterpret_cast<const float4*>(graph_embed + (size_t)b * 128);
    const float4 g0 = grow[0 * 8 + sub];
    const float4 g1 = grow[1 * 8 + sub];
    const float4 g2 = grow[2 * 8 + sub];
    const float4 g3 = grow[3 * 8 + sub];

#if __CUDA_ARCH__ >= 900
    cudaGridDependencySynchronize();   // wait for build_offsets completion
#endif
    // ---- offsets now valid ----
    const int start = g_offsets[b];
    const int end   = g_offsets[b + 1];

    float s = 0.0f;          // direct sum of exp(logit); fp32 range is sufficient
    float tlogit = 0.0f;
    bool  have_t = false;

    for (int chunk = start; chunk < end; chunk += 32) {
        // coalesced preload of up to 32 candidate indices (invalid -> row 0)
        const int tl_idx = chunk + lane;
        const int cvec = (tl_idx < end) ? __ldg(&cand_idx[tl_idx]) : 0;
        const int rem = end - chunk;   // > 0

        #pragma unroll
        for (int j = 0; j < 32; j += 8) {
            if (j >= rem) break;       // warp-uniform

            const int idxA = chunk + j + grp;
            const int idxB = chunk + j + 4 + grp;
            const bool vA = (idxA < end);
            const bool vB = (idxB < end);
            const int cA = __shfl_sync(0xFFFFFFFFu, cvec, j + grp);
            const int cB = __shfl_sync(0xFFFFFFFFu, cvec, j + 4 + grp);

            const float4* ta = reinterpret_cast<const float4*>(tpl + (size_t)cA * 128);
            const float4* tb = reinterpret_cast<const float4*>(tpl + (size_t)cB * 128);
            const float4 a0 = ta[0 * 8 + sub];
            const float4 a1 = ta[1 * 8 + sub];
            const float4 a2 = ta[2 * 8 + sub];
            const float4 a3 = ta[3 * 8 + sub];
            const float4 b0 = tb[0 * 8 + sub];
            const float4 b1 = tb[1 * 8 + sub];
            const float4 b2 = tb[2 * 8 + sub];
            const float4 b3 = tb[3 * 8 + sub];

            float dA;
            dA  = g0.x * a0.x; dA += g0.y * a0.y; dA += g0.z * a0.z; dA += g0.w * a0.w;
            dA += g1.x * a1.x; dA += g1.y * a1.y; dA += g1.z * a1.z; dA += g1.w * a1.w;
            dA += g2.x * a2.x; dA += g2.y * a2.y; dA += g2.z * a2.z; dA += g2.w * a2.w;
            dA += g3.x * a3.x; dA += g3.y * a3.y; dA += g3.z * a3.z; dA += g3.w * a3.w;

            float dB;
            dB  = g0.x * b0.x; dB += g0.y * b0.y; dB += g0.z * b0.z; dB += g0.w * b0.w;
            dB += g1.x * b1.x; dB += g1.y * b1.y; dB += g1.z * b1.z; dB += g1.w * b1.w;
            dB += g2.x * b2.x; dB += g2.y * b2.y; dB += g2.z * b2.z; dB += g2.w * b2.w;
            dB += g3.x * b3.x; dB += g3.y * b3.y; dB += g3.z * b3.z; dB += g3.w * b3.w;

            dA += __shfl_xor_sync(0xFFFFFFFFu, dA, 1);
            dB += __shfl_xor_sync(0xFFFFFFFFu, dB, 1);
            dA += __shfl_xor_sync(0xFFFFFFFFu, dA, 2);
            dB += __shfl_xor_sync(0xFFFFFFFFu, dB, 2);
            dA += __shfl_xor_sync(0xFFFFFFFFu, dA, 4);
            dB += __shfl_xor_sync(0xFFFFFFFFu, dB, 4);

            if (vA) {
                s += __expf(dA);
                if (idxA == tgt) { tlogit = dA; have_t = true; }
            }
            if (vB) {
                s += __expf(dB);
                if (idxB == tgt) { tlogit = dB; have_t = true; }
            }
        }
    }

    // total sum: the 4 groups hold distinct partial sums (identical within group)
    s += __shfl_xor_sync(0xFFFFFFFFu, s, 8);
    s += __shfl_xor_sync(0xFFFFFFFFu, s, 16);

    // broadcast target logit from whichever group found it
    const unsigned ball = __ballot_sync(0xFFFFFFFFu, have_t);
    const int src = __ffs(ball) - 1;   // tgt is always inside [start, end)
    const float tl = __shfl_sync(0xFFFFFFFFu, tlogit, src);

    if (lane == 0) out[b] = tl - logf(s);
}

extern "C" void kernel_launch(void* const* d_in, const int* in_sizes, int n_in,
                              void* d_out, int out_size) {
    const float* graph_embed = (const float*)d_in[0];
    const float* tpl         = (const float*)d_in[1];
    const int*   cand_idx    = (const int*)d_in[2];
    const int*   seg_ids     = (const int*)d_in[3];
    const int*   target_pos  = (const int*)d_in[4];
    float*       out         = (float*)d_out;

    const int T = in_sizes[2];
    const int B = in_sizes[4];

    const int n4 = (T + 3) / 4;
    build_offsets_kernel<<<(n4 + 255) / 256, 256>>>(seg_ids, T, B);

    // Main kernel with programmatic dependent launch: overlaps its
    // offset-independent prologue with build_offsets_kernel.
    const int warps_per_cta = THREADS / 32;
    const int nblocks = (B + warps_per_cta - 1) / warps_per_cta;

    cudaLaunchConfig_t cfg = {};
    cfg.gridDim  = dim3((unsigned)nblocks, 1, 1);
    cfg.blockDim = dim3(THREADS, 1, 1);
    cfg.dynamicSmemBytes = 0;
    cfg.stream = 0;
    cudaLaunchAttribute attrs[1];
    attrs[0].id = cudaLaunchAttributeProgrammaticStreamSerialization;
    attrs[0].val.programmaticStreamSerializationAllowed = 1;
    cfg.attrs = attrs;
    cfg.numAttrs = 1;

    cudaLaunchKernelEx(&cfg, seg_logsoftmax_kernel,
                       graph_embed, tpl, cand_idx, target_pos, out, B);
}

// round 13
// speedup vs baseline: 1.0571x; 1.0195x over previous
#include <cuda_runtime.h>
#include <math_constants.h>

// Inputs (metadata order):
//  0: graph_embed   [B, 128]  f32
//  1: tpl_embedding [V+1,128] f32
//  2: cand_idx      [T]       i32
//  3: seg_ids       [T]       i32 (sorted)
//  4: target_pos    [B]       i32 (absolute index into T)
// Output: [B] f32  log_prob of target per segment.

#define MAX_B 8192
__device__ int g_offsets[MAX_B + 1];

// Vectorized boundary finder: each thread scans 4 consecutive seg_ids.
// Triggers programmatic launch of the main kernel ASAP.
__global__ void build_offsets_kernel(const int* __restrict__ seg_ids, int T, int B) {
#if __CUDA_ARCH__ >= 900
    cudaTriggerProgrammaticLaunchCompletion();
#endif
    const int t4 = (blockIdx.x * blockDim.x + threadIdx.x) * 4;
    if (t4 >= T) return;
    const int4 v = *reinterpret_cast<const int4*>(seg_ids + t4);
    if (t4 == 0) {
        g_offsets[0] = 0;
        g_offsets[B] = T;
    } else {
        const int prev = __ldg(&seg_ids[t4 - 1]);
        if (v.x != prev) g_offsets[v.x] = t4;
    }
    if (v.y != v.x) g_offsets[v.y] = t4 + 1;
    if (v.z != v.y) g_offsets[v.z] = t4 + 2;
    if (v.w != v.z) g_offsets[v.w] = t4 + 3;
}

#define THREADS 64   // 2 warps per CTA, one segment per warp

// One WARP per segment. 8 lanes per candidate.
// Full 32-candidate chunks run a branch-free body (ptxas can batch gathers
// across all four 8-candidate substeps); the single tail chunk runs the
// guarded body with zero padded traffic.
__global__ __launch_bounds__(THREADS)
void seg_logsoftmax_kernel(const float* __restrict__ graph_embed,
                           const float* __restrict__ tpl,
                           const int*   __restrict__ cand_idx,
                           const int*   __restrict__ target_pos,
                           float*       __restrict__ out,
                           int B) {
    const int lane = threadIdx.x & 31;
    const int warp = threadIdx.x >> 5;
    const int b    = blockIdx.x * (THREADS / 32) + warp;
    if (b >= B) {
#if __CUDA_ARCH__ >= 900
        cudaGridDependencySynchronize();
#endif
        return;
    }

    const int sub = lane & 7;   // position within candidate group (8 lanes/cand)
    const int grp = lane >> 3;  // candidate group 0..3

    // ---- offset-independent work (overlaps with prologue kernel) ----
    const int tgt = target_pos[b];

    const float4* grow = reinterpret_cast<const float4*>(graph_embed + (size_t)b * 128);
    const float4 g0 = grow[0 * 8 + sub];
    const float4 g1 = grow[1 * 8 + sub];
    const float4 g2 = grow[2 * 8 + sub];
    const float4 g3 = grow[3 * 8 + sub];

#if __CUDA_ARCH__ >= 900
    cudaGridDependencySynchronize();   // wait for build_offsets completion
#endif
    const int start = g_offsets[b];
    const int end   = g_offsets[b + 1];

    float s = 0.0f;          // direct sum of exp(logit); fp32 range is sufficient
    float tlogit = 0.0f;
    bool  have_t = false;

    int chunk = start;

    // ---- full chunks: branch-free body, maximal load batching ----
    for (; chunk + 32 <= end; chunk += 32) {
        const int cvec = __ldg(&cand_idx[chunk + lane]);

        #pragma unroll
        for (int j = 0; j < 32; j += 8) {
            const int idxA = chunk + j + grp;
            const int idxB = chunk + j + 4 + grp;
            const int cA = __shfl_sync(0xFFFFFFFFu, cvec, j + grp);
            const int cB = __shfl_sync(0xFFFFFFFFu, cvec, j + 4 + grp);

            const float4* ta = reinterpret_cast<const float4*>(tpl + (size_t)cA * 128);
            const float4* tb = reinterpret_cast<const float4*>(tpl + (size_t)cB * 128);
            const float4 a0 = ta[0 * 8 + sub];
            const float4 a1 = ta[1 * 8 + sub];
            const float4 a2 = ta[2 * 8 + sub];
            const float4 a3 = ta[3 * 8 + sub];
            const float4 b0 = tb[0 * 8 + sub];
            const float4 b1 = tb[1 * 8 + sub];
            const float4 b2 = tb[2 * 8 + sub];
            const float4 b3 = tb[3 * 8 + sub];

            float dA;
            dA  = g0.x * a0.x; dA += g0.y * a0.y; dA += g0.z * a0.z; dA += g0.w * a0.w;
            dA += g1.x * a1.x; dA += g1.y * a1.y; dA += g1.z * a1.z; dA += g1.w * a1.w;
            dA += g2.x * a2.x; dA += g2.y * a2.y; dA += g2.z * a2.z; dA += g2.w * a2.w;
            dA += g3.x * a3.x; dA += g3.y * a3.y; dA += g3.z * a3.z; dA += g3.w * a3.w;

            float dB;
            dB  = g0.x * b0.x; dB += g0.y * b0.y; dB += g0.z * b0.z; dB += g0.w * b0.w;
            dB += g1.x * b1.x; dB += g1.y * b1.y; dB += g1.z * b1.z; dB += g1.w * b1.w;
            dB += g2.x * b2.x; dB += g2.y * b2.y; dB += g2.z * b2.z; dB += g2.w * b2.w;
            dB += g3.x * b3.x; dB += g3.y * b3.y; dB += g3.z * b3.z; dB += g3.w * b3.w;

            dA += __shfl_xor_sync(0xFFFFFFFFu, dA, 1);
            dB += __shfl_xor_sync(0xFFFFFFFFu, dB, 1);
            dA += __shfl_xor_sync(0xFFFFFFFFu, dA, 2);
            dB += __shfl_xor_sync(0xFFFFFFFFu, dB, 2);
            dA += __shfl_xor_sync(0xFFFFFFFFu, dA, 4);
            dB += __shfl_xor_sync(0xFFFFFFFFu, dB, 4);

            s += __expf(dA);
            s += __expf(dB);
            if (idxA == tgt) { tlogit = dA; have_t = true; }
            if (idxB == tgt) { tlogit = dB; have_t = true; }
        }
    }

    // ---- tail chunk (< 32 candidates): guarded body, no padded traffic ----
    if (chunk < end) {
        const int tl_idx = chunk + lane;
        const int cvec = (tl_idx < end) ? __ldg(&cand_idx[tl_idx]) : 0;
        const int rem = end - chunk;   // 1..31

        #pragma unroll
        for (int j = 0; j < 32; j += 8) {
            if (j >= rem) break;       // warp-uniform

            const int idxA = chunk + j + grp;
            const int idxB = chunk + j + 4 + grp;
            const bool vA = (idxA < end);
            const bool vB = (idxB < end);
            const int cA = __shfl_sync(0xFFFFFFFFu, cvec, j + grp);
            const int cB = __shfl_sync(0xFFFFFFFFu, cvec, j + 4 + grp);

            const float4* ta = reinterpret_cast<const float4*>(tpl + (size_t)cA * 128);
            const float4* tb = reinterpret_cast<const float4*>(tpl + (size_t)cB * 128);
            const float4 a0 = ta[0 * 8 + sub];
            const float4 a1 = ta[1 * 8 + sub];
            const float4 a2 = ta[2 * 8 + sub];
            const float4 a3 = ta[3 * 8 + sub];
            const float4 b0 = tb[0 * 8 + sub];
            const float4 b1 = tb[1 * 8 + sub];
            const float4 b2 = tb[2 * 8 + sub];
            const float4 b3 = tb[3 * 8 + sub];

            float dA;
            dA  = g0.x * a0.x; dA += g0.y * a0.y; dA += g0.z * a0.z; dA += g0.w * a0.w;
            dA += g1.x * a1.x; dA += g1.y * a1.y; dA += g1.z * a1.z; dA += g1.w * a1.w;
            dA += g2.x * a2.x; dA += g2.y * a2.y; dA += g2.z * a2.z; dA += g2.w * a2.w;
            dA += g3.x * a3.x; dA += g3.y * a3.y; dA += g3.z * a3.z; dA += g3.w * a3.w;

            float dB;
            dB  = g0.x * b0.x; dB += g0.y * b0.y; dB += g0.z * b0.z; dB += g0.w * b0.w;
            dB += g1.x * b1.x; dB += g1.y * b1.y; dB += g1.z * b1.z; dB += g1.w * b1.w;
            dB += g2.x * b2.x; dB += g2.y * b2.y; dB += g2.z * b2.z; dB += g2.w * b2.w;
            dB += g3.x * b3.x; dB += g3.y * b3.y; dB += g3.z * b3.z; dB += g3.w * b3.w;

            dA += __shfl_xor_sync(0xFFFFFFFFu, dA, 1);
            dB += __shfl_xor_sync(0xFFFFFFFFu, dB, 1);
            dA += __shfl_xor_sync(0xFFFFFFFFu, dA, 2);
            dB += __shfl_xor_sync(0xFFFFFFFFu, dB, 2);
            dA += __shfl_xor_sync(0xFFFFFFFFu, dA, 4);
            dB += __shfl_xor_sync(0xFFFFFFFFu, dB, 4);

            if (vA) {
                s += __expf(dA);
                if (idxA == tgt) { tlogit = dA; have_t = true; }
            }
            if (vB) {
                s += __expf(dB);
                if (idxB == tgt) { tlogit = dB; have_t = true; }
            }
        }
    }

    // total sum: the 4 groups hold distinct partial sums (identical within group)
    s += __shfl_xor_sync(0xFFFFFFFFu, s, 8);
    s += __shfl_xor_sync(0xFFFFFFFFu, s, 16);

    // broadcast target logit from whichever group found it
    const unsigned ball = __ballot_sync(0xFFFFFFFFu, have_t);
    const int src = __ffs(ball) - 1;   // tgt is always inside [start, end)
    const float tl = __shfl_sync(0xFFFFFFFFu, tlogit, src);

    if (lane == 0) out[b] = tl - logf(s);
}

extern "C" void kernel_launch(void* const* d_in, const int* in_sizes, int n_in,
                              void* d_out, int out_size) {
    const float* graph_embed = (const float*)d_in[0];
    const float* tpl         = (const float*)d_in[1];
    const int*   cand_idx    = (const int*)d_in[2];
    const int*   seg_ids     = (const int*)d_in[3];
    const int*   target_pos  = (const int*)d_in[4];
    float*       out         = (float*)d_out;

    const int T = in_sizes[2];
    const int B = in_sizes[4];

    const int n4 = (T + 3) / 4;
    build_offsets_kernel<<<(n4 + 255) / 256, 256>>>(seg_ids, T, B);

    // Main kernel with programmatic dependent launch: overlaps its
    // offset-independent prologue with build_offsets_kernel.
    const int warps_per_cta = THREADS / 32;
    const int nblocks = (B + warps_per_cta - 1) / warps_per_cta;

    cudaLaunchConfig_t cfg = {};
    cfg.gridDim  = dim3((unsigned)nblocks, 1, 1);
    cfg.blockDim = dim3(THREADS, 1, 1);
    cfg.dynamicSmemBytes = 0;
    cfg.stream = 0;
    cudaLaunchAttribute attrs[1];
    attrs[0].id = cudaLaunchAttributeProgrammaticStreamSerialization;
    attrs[0].val.programmaticStreamSerializationAllowed = 1;
    cfg.attrs = attrs;
    cfg.numAttrs = 1;

    cudaLaunchKernelEx(&cfg, seg_logsoftmax_kernel,
                       graph_embed, tpl, cand_idx, target_pos, out, B);
}